// round 3
// baseline (speedup 1.0000x reference)
#include <cuda_runtime.h>
#include <math.h>
#include <stdint.h>

#define N_   64
#define C_   512
#define P_   1024
#define KA   65     // clusters incl. ghost
#define KC   64     // kept clusters
#define EPSF 1e-12f
#define QSPLIT 4    // p-splits for k_agg

// ---------------- scratch (device globals: allocation-free) ----------------
__device__ float g_inv[N_ * P_];                    // per-pixel 1/||x||
__device__ float g_a[N_ * KC * P_];                 // 16.8 MB softmax weights
__device__ float g_asum[N_ * KC];                   // sum_p a[k,p]
__device__ float g_aggp[QSPLIT * N_ * KC * C_];     // 33.5 MB partial aggregation
__device__ float g_nsq[N_];                         // per-sample sumsq accumulator

#define FMA2(d, a, b) asm("fma.rn.f32x2 %0, %1, %2, %0;" : "+l"(d) : "l"(a), "l"(b))
#define PACK2(d, lo, hi) asm("mov.b64 %0, {%1, %2};" : "=l"(d) : "f"(lo), "f"(hi))
#define UNPACK2(lo, hi, s) asm("mov.b64 {%0, %1}, %2;" : "=f"(lo), "=f"(hi) : "l"(s))
#define LDSV2U64(a, b, addr) \
    asm volatile("ld.shared.v2.b64 {%0, %1}, [%2];" : "=l"(a), "=l"(b) : "r"(addr))

// ---------------- kernel 1: logits + softmax -> a  (norm fused in) ----------------
// grid (64, 8) x 128 threads; thread = one pixel; 65 accumulators (32 packed + 1),
// conv_w staged per-64-channel chunk in smem, packed f32x2 FMA over k.
__global__ void __launch_bounds__(128) k_logits(const float* __restrict__ x,
                                                const float* __restrict__ w,
                                                const float* __restrict__ b) {
    __shared__ float ws[64 * 68];   // [cc][k], row pad 68 floats (272B, 16B-aligned)
    __shared__ float bs[KA];
    int n = blockIdx.x;
    int p = blockIdx.y * 128 + threadIdx.x;
    if (threadIdx.x < KA) bs[threadIdx.x] = b[threadIdx.x];

    unsigned long long acc2[32];
#pragma unroll
    for (int j = 0; j < 32; j++) acc2[j] = 0ULL;   // (0.f,0.f)
    float acc64 = 0.f, sumsq = 0.f;

    const float* xp = x + (size_t)n * C_ * P_ + p;
    uint32_t wsb = (uint32_t)__cvta_generic_to_shared(ws);

    for (int c0 = 0; c0 < C_; c0 += 64) {
        __syncthreads();
        for (int i = threadIdx.x; i < KA * 64; i += 128) {
            int k = i >> 6, cc = i & 63;
            ws[cc * 68 + k] = w[k * C_ + c0 + cc];
        }
        __syncthreads();
#pragma unroll 4
        for (int cc = 0; cc < 64; cc++) {
            float xv = xp[(size_t)(c0 + cc) * P_];
            sumsq = fmaf(xv, xv, sumsq);
            unsigned long long xv2;
            PACK2(xv2, xv, xv);
            uint32_t rb = wsb + cc * 272;
#pragma unroll
            for (int j = 0; j < 16; j++) {
                unsigned long long w0, w1;
                LDSV2U64(w0, w1, rb + j * 16);
                FMA2(acc2[2 * j], xv2, w0);
                FMA2(acc2[2 * j + 1], xv2, w1);
            }
            acc64 = fmaf(ws[cc * 68 + 64], xv, acc64);
        }
    }

    float inv = 1.f / fmaxf(sqrtf(sumsq), EPSF);
    g_inv[n * P_ + p] = inv;

    float l[KA];
#pragma unroll
    for (int j = 0; j < 32; j++) {
        float lo, hi;
        UNPACK2(lo, hi, acc2[j]);
        l[2 * j]     = fmaf(lo, inv, bs[2 * j]);
        l[2 * j + 1] = fmaf(hi, inv, bs[2 * j + 1]);
    }
    l[64] = fmaf(acc64, inv, bs[64]);

    float m = l[0];
#pragma unroll
    for (int k = 1; k < KA; k++) m = fmaxf(m, l[k]);
    float s = 0.f;
#pragma unroll
    for (int k = 0; k < KA; k++) {
        float e = __expf(l[k] - m);
        l[k] = e;
        s += e;
    }
    float rs = 1.f / s;

    float* ao = g_a + (size_t)n * KC * P_ + p;
#pragma unroll
    for (int k = 0; k < KC; k++) ao[(size_t)k * P_] = l[k] * rs;
}

// ---------------- kernel 2: asum[n][k] = sum_p a (+ reset g_nsq) ----------------
__global__ void __launch_bounds__(256) k_asum() {
    int n = blockIdx.x, k = blockIdx.y;
    int tid = threadIdx.x;
    if (k == 0 && tid == 0) g_nsq[n] = 0.f;
    const float* ap = g_a + ((size_t)n * KC + k) * P_;
    float s = 0.f;
    for (int p = tid; p < P_; p += 256) s += ap[p];
#pragma unroll
    for (int o = 16; o; o >>= 1) s += __shfl_xor_sync(0xFFFFFFFFu, s, o);
    __shared__ float red[8];
    if ((tid & 31) == 0) red[tid >> 5] = s;
    __syncthreads();
    if (tid == 0) {
        float t = 0.f;
#pragma unroll
        for (int i = 0; i < 8; i++) t += red[i];
        g_asum[n * KC + k] = t;
    }
}

// ---------------- kernel 3: aggregation GEMM (p-split x4, f32x2 packed) ----------------
// aggp[q][n][k][c] = sum_{p in quarter q} a[k,p] * x[c,p] * inv[p]
// grid (64, 4, 4) x 256 threads; tile 64k x 128c x 256p; thread = 4k x 8c.
__global__ void __launch_bounds__(256) k_agg(const float* __restrict__ x) {
    __shared__ float as_[32 * 68];    // [pp][k]  row 272B
    __shared__ float xs[32 * 132];    // [pp][c]  row 528B, inv folded in
    int n = blockIdx.x;
    int cbase = blockIdx.y * 128;
    int q = blockIdx.z;
    int tid = threadIdx.x;
    int tx = tid & 15;        // c group: 8 c's
    int ty = tid >> 4;        // k group: 4 k's

    unsigned long long acc2[4][4];    // [k][c-pair]
#pragma unroll
    for (int i = 0; i < 4; i++)
#pragma unroll
        for (int j = 0; j < 4; j++) acc2[i][j] = 0ULL;

    uint32_t asb = (uint32_t)__cvta_generic_to_shared(as_);
    uint32_t xsb = (uint32_t)__cvta_generic_to_shared(xs);
    int p_end = q * 256 + 256;

    for (int p0 = q * 256; p0 < p_end; p0 += 32) {
        __syncthreads();
        for (int i = tid; i < KC * 32; i += 256) {
            int k = i >> 5, pp = i & 31;
            as_[pp * 68 + k] = g_a[((size_t)n * KC + k) * P_ + p0 + pp];
        }
        for (int i = tid; i < 128 * 32; i += 256) {
            int c = i >> 5, pp = i & 31;
            xs[pp * 132 + c] =
                x[((size_t)n * C_ + cbase + c) * P_ + p0 + pp] * g_inv[n * P_ + p0 + pp];
        }
        __syncthreads();
#pragma unroll 4
        for (int pp = 0; pp < 32; pp++) {
            float4 av = *reinterpret_cast<const float4*>(as_ + pp * 68 + ty * 4);
            unsigned long long a0, a1, a2, a3;
            PACK2(a0, av.x, av.x);
            PACK2(a1, av.y, av.y);
            PACK2(a2, av.z, av.z);
            PACK2(a3, av.w, av.w);
            unsigned long long x0, x1, x2, x3;
            uint32_t xr = xsb + pp * 528 + tx * 32;
            LDSV2U64(x0, x1, xr);
            LDSV2U64(x2, x3, xr + 16);
            FMA2(acc2[0][0], a0, x0); FMA2(acc2[0][1], a0, x1);
            FMA2(acc2[0][2], a0, x2); FMA2(acc2[0][3], a0, x3);
            FMA2(acc2[1][0], a1, x0); FMA2(acc2[1][1], a1, x1);
            FMA2(acc2[1][2], a1, x2); FMA2(acc2[1][3], a1, x3);
            FMA2(acc2[2][0], a2, x0); FMA2(acc2[2][1], a2, x1);
            FMA2(acc2[2][2], a2, x2); FMA2(acc2[2][3], a2, x3);
            FMA2(acc2[3][0], a3, x0); FMA2(acc2[3][1], a3, x1);
            FMA2(acc2[3][2], a3, x2); FMA2(acc2[3][3], a3, x3);
        }
    }
#pragma unroll
    for (int i = 0; i < 4; i++) {
        int k = ty * 4 + i;
        float v[8];
#pragma unroll
        for (int j = 0; j < 4; j++) UNPACK2(v[2 * j], v[2 * j + 1], acc2[i][j]);
        float* dst = g_aggp + (((size_t)q * N_ + n) * KC + k) * C_ + cbase + tx * 8;
        *reinterpret_cast<float4*>(dst)     = make_float4(v[0], v[1], v[2], v[3]);
        *reinterpret_cast<float4*>(dst + 4) = make_float4(v[4], v[5], v[6], v[7]);
    }
}

// ---------------- kernel 4: partial-sum + centroid subtract + per-row L2 ----------------
// grid (64, 64) x 128 threads; thread handles 4 c's
__global__ void __launch_bounds__(128) k_rownorm(const float* __restrict__ cent,
                                                 float* __restrict__ out) {
    int n = blockIdx.x, k = blockIdx.y;
    int tid = threadIdx.x;
    float as = g_asum[n * KC + k];
    float v[4];
    float s = 0.f;
    size_t base = ((size_t)n * KC + k) * C_;
    const size_t qstride = (size_t)N_ * KC * C_;
#pragma unroll
    for (int j = 0; j < 4; j++) {
        int c = tid + j * 128;
        float val = g_aggp[base + c] + g_aggp[qstride + base + c] +
                    g_aggp[2 * qstride + base + c] + g_aggp[3 * qstride + base + c] -
                    as * cent[k * C_ + c];
        v[j] = val;
        s = fmaf(val, val, s);
    }
#pragma unroll
    for (int o = 16; o; o >>= 1) s += __shfl_xor_sync(0xFFFFFFFFu, s, o);
    __shared__ float red[4];
    __shared__ float tot;
    if ((tid & 31) == 0) red[tid >> 5] = s;
    __syncthreads();
    if (tid == 0) tot = red[0] + red[1] + red[2] + red[3];
    __syncthreads();
    float total = tot;
    float invn = 1.f / fmaxf(sqrtf(total), EPSF);
#pragma unroll
    for (int j = 0; j < 4; j++) {
        int c = tid + j * 128;
        out[(size_t)n * KC * C_ + (size_t)k * C_ + c] = v[j] * invn;
    }
    if (tid == 0) atomicAdd(&g_nsq[n], total * invn * invn);
}

// ---------------- kernel 5: global L2 normalize ----------------
__global__ void __launch_bounds__(256) k_final(float* __restrict__ out) {
    int n = blockIdx.x;
    float scale = 1.f / fmaxf(sqrtf(g_nsq[n]), EPSF);
    size_t idx = (size_t)n * (KC * C_) + ((size_t)blockIdx.y * 256 + threadIdx.x) * 4;
    float4* o = reinterpret_cast<float4*>(out + idx);
    float4 v = *o;
    v.x *= scale; v.y *= scale; v.z *= scale; v.w *= scale;
    *o = v;
}

// ---------------- launch ----------------
extern "C" void kernel_launch(void* const* d_in, const int* in_sizes, int n_in,
                              void* d_out, int out_size) {
    const float* x    = (const float*)d_in[0];
    const float* w    = (const float*)d_in[1];
    const float* b    = (const float*)d_in[2];
    const float* cent = (const float*)d_in[3];
    float* out = (float*)d_out;

    k_logits<<<dim3(N_, 8), 128>>>(x, w, b);
    k_asum<<<dim3(N_, KC), 256>>>();
    k_agg<<<dim3(N_, 4, QSPLIT), 256>>>(x);
    k_rownorm<<<dim3(N_, KC), 128>>>(cent, out);
    k_final<<<dim3(N_, 32), 256>>>(out);
}

// round 7
// speedup vs baseline: 2.0272x; 2.0272x over previous
#include <cuda_runtime.h>
#include <cuda_bf16.h>
#include <mma.h>
#include <math.h>
#include <stdint.h>

using namespace nvcuda;

#define N_   64
#define C_   512
#define P_   1024
#define KA   65
#define KC   64
#define EPSF 1e-12f

// ---------------- scratch (device globals: allocation-free) ----------------
__device__ float         g_inv[N_ * P_];
__device__ __nv_bfloat16 g_a[N_ * KC * P_];      // softmax weights, bf16
__device__ float         g_asum[N_ * KC];
__device__ float         g_agg[N_ * KC * C_];
__device__ float         g_nsq[N_];

// ============ GEMM1: logits (tensor cores) + fused L2 norm + softmax ============
// Per CTA: sample n, 128-pixel tile.  D[p=128, k=80pad] = bf16(x^T) * bf16(w)^T,
// K = 512 channels in 8 chunks of 64.  4 warps, warp w owns pixel rows [32w, 32w+32).
#define LDA1 72      // smem leading dim for bf16 tiles (mult of 8; 144B rows)
#define LDO1 84      // smem leading dim for f32 out tile  (336B rows)
__global__ void __launch_bounds__(128) k_gemm1(const float* __restrict__ x,
                                               const float* __restrict__ w,
                                               const float* __restrict__ b) {
    // union: { ws[80][72]bf16 (11520B) | xa[128][72]bf16 (18432B) }  vs  outp[128][84]f32 (43008B)
    __shared__ __align__(16) char smbuf[43008];
    __shared__ float bs[KA];
    __nv_bfloat16* ws = reinterpret_cast<__nv_bfloat16*>(smbuf);
    __nv_bfloat16* xa = reinterpret_cast<__nv_bfloat16*>(smbuf + 11520);
    float* outp = reinterpret_cast<float*>(smbuf);

    int n = blockIdx.x;
    int pblk = blockIdx.y * 128;
    int tid = threadIdx.x;
    int wid = tid >> 5;
    int lane = tid & 31;
    if (tid < KA) bs[tid] = b[tid];

    wmma::fragment<wmma::accumulator, 16, 16, 16, float> acc[2][5];
#pragma unroll
    for (int i = 0; i < 2; i++)
#pragma unroll
        for (int j = 0; j < 5; j++) wmma::fill_fragment(acc[i][j], 0.f);

    float sumsq = 0.f;
    const float* xp = x + (size_t)n * C_ * P_ + pblk + tid;

    for (int ch = 0; ch < 8; ch++) {
        int c0 = ch * 64;
        __syncthreads();
        // stage w chunk: rows k=0..79 (65 real, rest zero), 64 c's per row
        for (int r = wid; r < 80; r += 4) {
            float f0 = 0.f, f1 = 0.f;
            if (r < KA) {
                float2 v = *reinterpret_cast<const float2*>(w + r * C_ + c0 + 2 * lane);
                f0 = v.x; f1 = v.y;
            }
            __nv_bfloat162 h = __floats2bfloat162_rn(f0, f1);
            *reinterpret_cast<uint32_t*>(&ws[r * LDA1 + 2 * lane]) =
                *reinterpret_cast<uint32_t*>(&h);
        }
        // stage x chunk: thread = pixel row, 64 c's (coalesced gmem reads over p)
#pragma unroll
        for (int j = 0; j < 32; j++) {
            float v0 = xp[(size_t)(c0 + 2 * j) * P_];
            float v1 = xp[(size_t)(c0 + 2 * j + 1) * P_];
            sumsq = fmaf(v0, v0, sumsq);
            sumsq = fmaf(v1, v1, sumsq);
            __nv_bfloat162 h = __floats2bfloat162_rn(v0, v1);
            *reinterpret_cast<uint32_t*>(&xa[tid * LDA1 + 2 * j]) =
                *reinterpret_cast<uint32_t*>(&h);
        }
        __syncthreads();
#pragma unroll
        for (int ks = 0; ks < 4; ks++) {
            wmma::fragment<wmma::matrix_a, 16, 16, 16, __nv_bfloat16, wmma::row_major> af[2];
#pragma unroll
            for (int i = 0; i < 2; i++)
                wmma::load_matrix_sync(af[i], xa + (32 * wid + 16 * i) * LDA1 + 16 * ks, LDA1);
#pragma unroll
            for (int j = 0; j < 5; j++) {
                wmma::fragment<wmma::matrix_b, 16, 16, 16, __nv_bfloat16, wmma::col_major> bf;
                wmma::load_matrix_sync(bf, ws + (16 * j) * LDA1 + 16 * ks, LDA1);
#pragma unroll
                for (int i = 0; i < 2; i++) wmma::mma_sync(acc[i][j], af[i], bf, acc[i][j]);
            }
        }
    }

    __syncthreads();   // smem reuse: bf16 tiles -> f32 out tile
#pragma unroll
    for (int i = 0; i < 2; i++)
#pragma unroll
        for (int j = 0; j < 5; j++)
            wmma::store_matrix_sync(outp + (32 * wid + 16 * i) * LDO1 + 16 * j,
                                    acc[i][j], LDO1, wmma::mem_row_major);
    __syncthreads();

    // epilogue: thread = pixel. logits = D*inv + b ; softmax over 65 ; store a (bf16)
    float inv = 1.f / fmaxf(sqrtf(sumsq), EPSF);
    g_inv[n * P_ + pblk + tid] = inv;

    float l[KA];
    const float* orow = outp + tid * LDO1;
#pragma unroll
    for (int k = 0; k < KA; k++) l[k] = fmaf(orow[k], inv, bs[k]);
    float m = l[0];
#pragma unroll
    for (int k = 1; k < KA; k++) m = fmaxf(m, l[k]);
    float s = 0.f;
#pragma unroll
    for (int k = 0; k < KA; k++) { float e = __expf(l[k] - m); l[k] = e; s += e; }
    float rs = 1.f / s;

    __nv_bfloat16* ao = g_a + (size_t)n * KC * P_ + pblk + tid;
#pragma unroll
    for (int k = 0; k < KC; k++) ao[(size_t)k * P_] = __float2bfloat16(l[k] * rs);
}

// ============ GEMM2: aggregation (tensor cores) ============
// Per CTA: sample n, 128-channel tile.  D[k=64, c=128] = a[k,p] * (x*inv)[c,p]^T,
// K = 1024 pixels in 16 chunks of 64.  4 warps, warp w owns cluster rows [16w, 16w+16).
__global__ void __launch_bounds__(128) k_gemm2(const float* __restrict__ x) {
    __shared__ __align__(16) __nv_bfloat16 xs[128 * LDA1];   // [c][p-chunk], 18432B

    int n = blockIdx.x;
    int cbase = blockIdx.y * 128;
    int tid = threadIdx.x;
    int wid = tid >> 5;
    int lane = tid & 31;

    wmma::fragment<wmma::accumulator, 16, 16, 16, float> acc[8];
#pragma unroll
    for (int j = 0; j < 8; j++) wmma::fill_fragment(acc[j], 0.f);

    const __nv_bfloat16* abase = g_a + ((size_t)n * KC + 16 * wid) * P_;

    for (int ch = 0; ch < 16; ch++) {
        int p0 = ch * 64;
        __syncthreads();
        float2 iv = *reinterpret_cast<const float2*>(g_inv + n * P_ + p0 + 2 * lane);
        for (int r = wid; r < 128; r += 4) {
            float2 xv = *reinterpret_cast<const float2*>(
                x + ((size_t)n * C_ + cbase + r) * P_ + p0 + 2 * lane);
            __nv_bfloat162 h = __floats2bfloat162_rn(xv.x * iv.x, xv.y * iv.y);
            *reinterpret_cast<uint32_t*>(&xs[r * LDA1 + 2 * lane]) =
                *reinterpret_cast<uint32_t*>(&h);
        }
        __syncthreads();
#pragma unroll
        for (int ks = 0; ks < 4; ks++) {
            wmma::fragment<wmma::matrix_a, 16, 16, 16, __nv_bfloat16, wmma::row_major> af;
            wmma::load_matrix_sync(af, abase + p0 + 16 * ks, P_);
#pragma unroll
            for (int j = 0; j < 8; j++) {
                wmma::fragment<wmma::matrix_b, 16, 16, 16, __nv_bfloat16, wmma::col_major> bf;
                wmma::load_matrix_sync(bf, xs + (16 * j) * LDA1 + 16 * ks, LDA1);
                wmma::mma_sync(acc[j], af, bf, acc[j]);
            }
        }
    }

    float* dbase = g_agg + ((size_t)n * KC + 16 * wid) * C_ + cbase;
#pragma unroll
    for (int j = 0; j < 8; j++)
        wmma::store_matrix_sync(dbase + 16 * j, acc[j], C_, wmma::mem_row_major);
}

// ---------------- asum[n][k] = sum_p a (bf16 in) + reset g_nsq ----------------
__global__ void __launch_bounds__(256) k_asum() {
    int n = blockIdx.x, k = blockIdx.y;
    int tid = threadIdx.x;
    if (k == 0 && tid == 0) g_nsq[n] = 0.f;
    const __nv_bfloat16* ap = g_a + ((size_t)n * KC + k) * P_;
    float s = 0.f;
    for (int p = tid; p < P_; p += 256) s += __bfloat162float(ap[p]);
#pragma unroll
    for (int o = 16; o; o >>= 1) s += __shfl_xor_sync(0xFFFFFFFFu, s, o);
    __shared__ float red[8];
    if ((tid & 31) == 0) red[tid >> 5] = s;
    __syncthreads();
    if (tid == 0) {
        float t = 0.f;
#pragma unroll
        for (int i = 0; i < 8; i++) t += red[i];
        g_asum[n * KC + k] = t;
    }
}

// ---------------- centroid subtract + per-row L2 ----------------
__global__ void __launch_bounds__(128) k_rownorm(const float* __restrict__ cent,
                                                 float* __restrict__ out) {
    int n = blockIdx.x, k = blockIdx.y;
    int tid = threadIdx.x;
    float as = g_asum[n * KC + k];
    float v[4];
    float s = 0.f;
    size_t base = ((size_t)n * KC + k) * C_;
#pragma unroll
    for (int j = 0; j < 4; j++) {
        int c = tid + j * 128;
        float val = g_agg[base + c] - as * cent[k * C_ + c];
        v[j] = val;
        s = fmaf(val, val, s);
    }
#pragma unroll
    for (int o = 16; o; o >>= 1) s += __shfl_xor_sync(0xFFFFFFFFu, s, o);
    __shared__ float red[4];
    __shared__ float tot;
    if ((tid & 31) == 0) red[tid >> 5] = s;
    __syncthreads();
    if (tid == 0) tot = red[0] + red[1] + red[2] + red[3];
    __syncthreads();
    float total = tot;
    float invn = 1.f / fmaxf(sqrtf(total), EPSF);
#pragma unroll
    for (int j = 0; j < 4; j++) {
        int c = tid + j * 128;
        out[(size_t)n * KC * C_ + (size_t)k * C_ + c] = v[j] * invn;
    }
    if (tid == 0) atomicAdd(&g_nsq[n], total * invn * invn);
}

// ---------------- global L2 normalize ----------------
__global__ void __launch_bounds__(256) k_final(float* __restrict__ out) {
    int n = blockIdx.x;
    float scale = 1.f / fmaxf(sqrtf(g_nsq[n]), EPSF);
    size_t idx = (size_t)n * (KC * C_) + ((size_t)blockIdx.y * 256 + threadIdx.x) * 4;
    float4* o = reinterpret_cast<float4*>(out + idx);
    float4 v = *o;
    v.x *= scale; v.y *= scale; v.z *= scale; v.w *= scale;
    *o = v;
}

// ---------------- launch ----------------
extern "C" void kernel_launch(void* const* d_in, const int* in_sizes, int n_in,
                              void* d_out, int out_size) {
    const float* x    = (const float*)d_in[0];
    const float* w    = (const float*)d_in[1];
    const float* b    = (const float*)d_in[2];
    const float* cent = (const float*)d_in[3];
    float* out = (float*)d_out;

    k_gemm1<<<dim3(N_, 8), 128>>>(x, w, b);
    k_asum<<<dim3(N_, KC), 256>>>();
    k_gemm2<<<dim3(N_, 4), 128>>>(x);
    k_rownorm<<<dim3(N_, KC), 128>>>(cent, out);
    k_final<<<dim3(N_, 32), 256>>>(out);
}

// round 8
// speedup vs baseline: 3.2942x; 1.6250x over previous
#include <cuda_runtime.h>
#include <cuda_bf16.h>
#include <mma.h>
#include <math.h>
#include <stdint.h>

using namespace nvcuda;

#define N_   64
#define C_   512
#define P_   1024
#define KA   65
#define KC   64
#define EPSF 1e-12f

// ---------------- scratch (device globals: allocation-free) ----------------
__device__ float         g_inv[N_ * P_];
__device__ __nv_bfloat16 g_a[N_ * KC * P_];      // softmax weights, bf16
__device__ float         g_agg[N_ * KC * C_];
__device__ float         g_nsq[N_];

#define LDA1 72      // smem leading dim for bf16 tiles (144B rows)
#define LDO1 84      // smem leading dim for f32 out tile (336B rows)

// ============ GEMM1: logits (tensor cores) + fused L2 norm + softmax ============
// Per CTA: sample n, 128-pixel tile.  D[p=128, k=80pad] = bf16(x^T) * bf16(w)^T,
// K = 512 channels in 8 chunks of 64.  Software-pipelined: loads for chunk ch+1
// are issued before the mma phase of chunk ch.
__global__ void __launch_bounds__(128) k_gemm1(const float* __restrict__ x,
                                               const float* __restrict__ w,
                                               const float* __restrict__ b) {
    // union: { ws[80][72]bf16 (11520B) | xa[128][72]bf16 (18432B) } vs outp[128][84]f32
    __shared__ __align__(16) char smbuf[43008];
    __shared__ float bs[KA];
    __nv_bfloat16* ws = reinterpret_cast<__nv_bfloat16*>(smbuf);
    __nv_bfloat16* xa = reinterpret_cast<__nv_bfloat16*>(smbuf + 11520);
    float* outp = reinterpret_cast<float*>(smbuf);

    int n = blockIdx.x;
    int pblk = blockIdx.y * 128;
    int tid = threadIdx.x;
    int wid = tid >> 5;
    int lane = tid & 31;
    if (tid < KA) bs[tid] = b[tid];

    wmma::fragment<wmma::accumulator, 16, 16, 16, float> acc[2][5];
#pragma unroll
    for (int i = 0; i < 2; i++)
#pragma unroll
        for (int j = 0; j < 5; j++) wmma::fill_fragment(acc[i][j], 0.f);

    float sumsq = 0.f;
    const float* xp = x + (size_t)n * C_ * P_ + pblk + tid;
    uint32_t xr[32];   // packed bf16x2: 64 channels of this thread's pixel
    uint32_t wr[20];   // packed bf16x2: this thread's share of the w chunk

#define G1_LOAD(c0_)                                                           \
    do {                                                                       \
        _Pragma("unroll")                                                      \
        for (int j = 0; j < 32; j++) {                                         \
            float v0 = xp[(size_t)((c0_) + 2 * j) * P_];                       \
            float v1 = xp[(size_t)((c0_) + 2 * j + 1) * P_];                   \
            sumsq = fmaf(v0, v0, sumsq);                                       \
            sumsq = fmaf(v1, v1, sumsq);                                       \
            __nv_bfloat162 h = __floats2bfloat162_rn(v0, v1);                  \
            xr[j] = *reinterpret_cast<uint32_t*>(&h);                          \
        }                                                                      \
        _Pragma("unroll")                                                      \
        for (int i = 0; i < 20; i++) {                                         \
            int r = wid + 4 * i;                                               \
            float f0 = 0.f, f1 = 0.f;                                          \
            if (r < KA) {                                                      \
                float2 v = *reinterpret_cast<const float2*>(                   \
                    w + r * C_ + (c0_) + 2 * lane);                            \
                f0 = v.x; f1 = v.y;                                            \
            }                                                                  \
            __nv_bfloat162 h = __floats2bfloat162_rn(f0, f1);                  \
            wr[i] = *reinterpret_cast<uint32_t*>(&h);                          \
        }                                                                      \
    } while (0)

    G1_LOAD(0);

    for (int ch = 0; ch < 8; ch++) {
        __syncthreads();   // previous mma done reading smem
#pragma unroll
        for (int j = 0; j < 32; j++)
            *reinterpret_cast<uint32_t*>(&xa[tid * LDA1 + 2 * j]) = xr[j];
#pragma unroll
        for (int i = 0; i < 20; i++)
            *reinterpret_cast<uint32_t*>(&ws[(wid + 4 * i) * LDA1 + 2 * lane]) = wr[i];
        __syncthreads();

        if (ch < 7) G1_LOAD((ch + 1) * 64);   // LDGs in flight during mma below

#pragma unroll
        for (int ks = 0; ks < 4; ks++) {
            wmma::fragment<wmma::matrix_a, 16, 16, 16, __nv_bfloat16, wmma::row_major> af[2];
#pragma unroll
            for (int i = 0; i < 2; i++)
                wmma::load_matrix_sync(af[i], xa + (32 * wid + 16 * i) * LDA1 + 16 * ks, LDA1);
#pragma unroll
            for (int j = 0; j < 5; j++) {
                wmma::fragment<wmma::matrix_b, 16, 16, 16, __nv_bfloat16, wmma::col_major> bf;
                wmma::load_matrix_sync(bf, ws + (16 * j) * LDA1 + 16 * ks, LDA1);
#pragma unroll
                for (int i = 0; i < 2; i++) wmma::mma_sync(acc[i][j], af[i], bf, acc[i][j]);
            }
        }
    }
#undef G1_LOAD

    __syncthreads();   // smem reuse: bf16 tiles -> f32 out tile
#pragma unroll
    for (int i = 0; i < 2; i++)
#pragma unroll
        for (int j = 0; j < 5; j++)
            wmma::store_matrix_sync(outp + (32 * wid + 16 * i) * LDO1 + 16 * j,
                                    acc[i][j], LDO1, wmma::mem_row_major);
    __syncthreads();

    // epilogue: thread = pixel. logits = D*inv + b ; softmax over 65 ; store a (bf16)
    float inv = 1.f / fmaxf(sqrtf(sumsq), EPSF);
    g_inv[n * P_ + pblk + tid] = inv;

    float l[KA];
    const float* orow = outp + tid * LDO1;
#pragma unroll
    for (int k = 0; k < KA; k++) l[k] = fmaf(orow[k], inv, bs[k]);
    float m = l[0];
#pragma unroll
    for (int k = 1; k < KA; k++) m = fmaxf(m, l[k]);
    float s = 0.f;
#pragma unroll
    for (int k = 0; k < KA; k++) { float e = __expf(l[k] - m); l[k] = e; s += e; }
    float rs = 1.f / s;

    __nv_bfloat16* ao = g_a + (size_t)n * KC * P_ + pblk + tid;
#pragma unroll
    for (int k = 0; k < KC; k++) ao[(size_t)k * P_] = __float2bfloat16(l[k] * rs);
}

// ============ GEMM2: aggregation (tensor cores), pipelined ============
// Per CTA: sample n, 128-channel tile.  D[k=64, c=128] = a[k,p] * (x*inv)[c,p]^T,
// K = 1024 pixels in 16 chunks of 64.  Warp w owns cluster rows [16w, 16w+16).
__global__ void __launch_bounds__(128) k_gemm2(const float* __restrict__ x) {
    __shared__ __align__(16) __nv_bfloat16 xs[128 * LDA1];   // [c][p-chunk]

    int n = blockIdx.x;
    int cbase = blockIdx.y * 128;
    int tid = threadIdx.x;
    int wid = tid >> 5;
    int lane = tid & 31;
    if (blockIdx.y == 0 && tid == 0) g_nsq[n] = 0.f;   // reset before k_rownorm

    wmma::fragment<wmma::accumulator, 16, 16, 16, float> acc[8];
#pragma unroll
    for (int j = 0; j < 8; j++) wmma::fill_fragment(acc[j], 0.f);

    const __nv_bfloat16* abase = g_a + ((size_t)n * KC + 16 * wid) * P_;
    uint32_t xr[32];

#define G2_LOAD(p0_)                                                           \
    do {                                                                       \
        float2 iv = *reinterpret_cast<const float2*>(g_inv + n * P_ + (p0_) + 2 * lane); \
        _Pragma("unroll")                                                      \
        for (int rr = 0; rr < 32; rr++) {                                      \
            int r = wid + 4 * rr;                                              \
            float2 xv = *reinterpret_cast<const float2*>(                      \
                x + ((size_t)n * C_ + cbase + r) * P_ + (p0_) + 2 * lane);     \
            __nv_bfloat162 h = __floats2bfloat162_rn(xv.x * iv.x, xv.y * iv.y);\
            xr[rr] = *reinterpret_cast<uint32_t*>(&h);                         \
        }                                                                      \
    } while (0)

    G2_LOAD(0);

    for (int ch = 0; ch < 16; ch++) {
        __syncthreads();
#pragma unroll
        for (int rr = 0; rr < 32; rr++)
            *reinterpret_cast<uint32_t*>(&xs[(wid + 4 * rr) * LDA1 + 2 * lane]) = xr[rr];
        __syncthreads();

        int p0 = ch * 64;
        if (ch < 15) G2_LOAD((ch + 1) * 64);   // LDGs in flight during mma below

        wmma::fragment<wmma::matrix_a, 16, 16, 16, __nv_bfloat16, wmma::row_major> af[4];
#pragma unroll
        for (int ks = 0; ks < 4; ks++)
            wmma::load_matrix_sync(af[ks], abase + p0 + 16 * ks, P_);
#pragma unroll
        for (int ks = 0; ks < 4; ks++) {
#pragma unroll
            for (int j = 0; j < 8; j++) {
                wmma::fragment<wmma::matrix_b, 16, 16, 16, __nv_bfloat16, wmma::col_major> bf;
                wmma::load_matrix_sync(bf, xs + (16 * j) * LDA1 + 16 * ks, LDA1);
                wmma::mma_sync(acc[j], af[ks], bf, acc[j]);
            }
        }
    }
#undef G2_LOAD

    float* dbase = g_agg + ((size_t)n * KC + 16 * wid) * C_ + cbase;
#pragma unroll
    for (int j = 0; j < 8; j++)
        wmma::store_matrix_sync(dbase + 16 * j, acc[j], C_, wmma::mem_row_major);
}

// ------- centroid subtract + per-row L2 (asum computed inline from g_a) -------
__global__ void __launch_bounds__(128) k_rownorm(const float* __restrict__ cent,
                                                 float* __restrict__ out) {
    int n = blockIdx.x, k = blockIdx.y;
    int tid = threadIdx.x;
    __shared__ float red[4];
    __shared__ float bcast;

    // asum[n][k] = sum_p a[k][p] : 1024 bf16 = 128 threads x uint4 (8 values)
    const __nv_bfloat16* ap = g_a + ((size_t)n * KC + k) * P_;
    uint4 u = reinterpret_cast<const uint4*>(ap)[tid];
    float asv = 0.f;
    {
        __nv_bfloat162 h;
        uint32_t parts[4] = {u.x, u.y, u.z, u.w};
#pragma unroll
        for (int i = 0; i < 4; i++) {
            h = *reinterpret_cast<__nv_bfloat162*>(&parts[i]);
            asv += __low2float(h) + __high2float(h);
        }
    }
#pragma unroll
    for (int o = 16; o; o >>= 1) asv += __shfl_xor_sync(0xFFFFFFFFu, asv, o);
    if ((tid & 31) == 0) red[tid >> 5] = asv;
    __syncthreads();
    if (tid == 0) bcast = red[0] + red[1] + red[2] + red[3];
    __syncthreads();
    float as = bcast;
    __syncthreads();   // protect red/bcast before reuse

    float v[4];
    float s = 0.f;
    size_t base = ((size_t)n * KC + k) * C_;
#pragma unroll
    for (int j = 0; j < 4; j++) {
        int c = tid + j * 128;
        float val = g_agg[base + c] - as * cent[k * C_ + c];
        v[j] = val;
        s = fmaf(val, val, s);
    }
#pragma unroll
    for (int o = 16; o; o >>= 1) s += __shfl_xor_sync(0xFFFFFFFFu, s, o);
    if ((tid & 31) == 0) red[tid >> 5] = s;
    __syncthreads();
    if (tid == 0) bcast = red[0] + red[1] + red[2] + red[3];
    __syncthreads();
    float total = bcast;
    float invn = 1.f / fmaxf(sqrtf(total), EPSF);
#pragma unroll
    for (int j = 0; j < 4; j++) {
        int c = tid + j * 128;
        out[(size_t)n * KC * C_ + (size_t)k * C_ + c] = v[j] * invn;
    }
    if (tid == 0) atomicAdd(&g_nsq[n], total * invn * invn);
}

// ---------------- global L2 normalize ----------------
__global__ void __launch_bounds__(256) k_final(float* __restrict__ out) {
    int n = blockIdx.x;
    float scale = 1.f / fmaxf(sqrtf(g_nsq[n]), EPSF);
    size_t idx = (size_t)n * (KC * C_) + ((size_t)blockIdx.y * 256 + threadIdx.x) * 4;
    float4* o = reinterpret_cast<float4*>(out + idx);
    float4 v = *o;
    v.x *= scale; v.y *= scale; v.z *= scale; v.w *= scale;
    *o = v;
}

// ---------------- launch ----------------
extern "C" void kernel_launch(void* const* d_in, const int* in_sizes, int n_in,
                              void* d_out, int out_size) {
    const float* x    = (const float*)d_in[0];
    const float* w    = (const float*)d_in[1];
    const float* b    = (const float*)d_in[2];
    const float* cent = (const float*)d_in[3];
    float* out = (float*)d_out;

    k_gemm1<<<dim3(N_, 8), 128>>>(x, w, b);
    k_gemm2<<<dim3(N_, 4), 128>>>(x);
    k_rownorm<<<dim3(N_, KC), 128>>>(cent, out);
    k_final<<<dim3(N_, 32), 256>>>(out);
}